// round 5
// baseline (speedup 1.0000x reference)
#include <cuda_runtime.h>

#define NN 100000
#define NE 3200000
#define NEG 0.2f

// ---- scratch (device globals; no allocations allowed) ----
__device__ __align__(16) float4 g_h1[NN * 2];     // h1 [NN,8]
__device__ float  g_as1[NN];
__device__ float  g_ad1[NN];
__device__ float  g_acc1[NN * 8];                 // sum ee*h1[src] per dst
__device__ float  g_den1[NN];
__device__ __align__(8)  float2 g_h2[NN];         // h2 [NN,2]
__device__ float  g_as2[NN];
__device__ float  g_ad2[NN];
__device__ float  g_acc2[NN * 2];
__device__ float  g_den2[NN];

// ---- layer-1 node kernel: h1 = x@W1, attention logits, zero accumulators ----
__global__ __launch_bounds__(128) void k_node1(
    const float* __restrict__ x, const float* __restrict__ W1,
    const float* __restrict__ as1, const float* __restrict__ ad1)
{
    __shared__ float xs[128 * 37];   // pad 36->37: conflict-free
    __shared__ float Ws[36 * 8];
    __shared__ float av[8], dv[8];
    const int t = threadIdx.x;
    const int base = blockIdx.x * 128;

    for (int i = t; i < 36 * 8; i += 128) Ws[i] = W1[i];
    if (t < 8) { av[t] = as1[t]; dv[t] = ad1[t]; }

    int nrows = NN - base; if (nrows > 128) nrows = 128;
    for (int i = t; i < nrows * 36; i += 128)
        xs[(i / 36) * 37 + (i % 36)] = x[base * 36 + i];
    __syncthreads();

    const int node = base + t;
    if (node >= NN) return;

    float h[8];
#pragma unroll
    for (int k = 0; k < 8; k++) h[k] = 0.f;
#pragma unroll
    for (int j = 0; j < 36; j++) {
        const float xv = xs[t * 37 + j];
#pragma unroll
        for (int k = 0; k < 8; k++) h[k] = fmaf(xv, Ws[j * 8 + k], h[k]);
    }
    g_h1[node * 2]     = make_float4(h[0], h[1], h[2], h[3]);
    g_h1[node * 2 + 1] = make_float4(h[4], h[5], h[6], h[7]);

    float s = 0.f, d = 0.f;
#pragma unroll
    for (int k = 0; k < 8; k++) { s = fmaf(h[k], av[k], s); d = fmaf(h[k], dv[k], d); }
    g_as1[node] = s;
    g_ad1[node] = d;

#pragma unroll
    for (int k = 0; k < 8; k++) g_acc1[node * 8 + k] = 0.f;
    g_den1[node] = 0.f;
    g_acc2[node * 2] = 0.f; g_acc2[node * 2 + 1] = 0.f;
    g_den2[node] = 0.f;
}

// ---- layer-1 edge kernel: denom += exp(leaky(e)); acc += exp*h1[src] ----
__global__ __launch_bounds__(256) void k_edge1(const int* __restrict__ ei)
{
    const int e = blockIdx.x * 256 + threadIdx.x;
    if (e >= NE) return;
    const int s = ei[e];
    const int d = ei[NE + e];
    if ((unsigned)s >= NN || (unsigned)d >= NN) return;  // safety clamp

    float ev = g_as1[s] + g_ad1[d];
    ev = ev > 0.f ? ev : NEG * ev;
    const float w = __expf(ev);

    atomicAdd(&g_den1[d], w);
    const float4 h0 = g_h1[s * 2];
    const float4 h1 = g_h1[s * 2 + 1];
    float* acc = &g_acc1[d * 8];
    atomicAdd(acc + 0, w * h0.x);
    atomicAdd(acc + 1, w * h0.y);
    atomicAdd(acc + 2, w * h0.z);
    atomicAdd(acc + 3, w * h0.w);
    atomicAdd(acc + 4, w * h1.x);
    atomicAdd(acc + 5, w * h1.y);
    atomicAdd(acc + 6, w * h1.z);
    atomicAdd(acc + 7, w * h1.w);
}

// ---- layer-2 node kernel: relu(agg1+b1) @ W2, attention logits ----
__global__ __launch_bounds__(256) void k_node2(
    const float* __restrict__ b1, const float* __restrict__ W2,
    const float* __restrict__ as2, const float* __restrict__ ad2)
{
    const int i = blockIdx.x * 256 + threadIdx.x;
    if (i >= NN) return;

    const float den = g_den1[i];
    const float inv = den > 0.f ? 1.0f / den : 0.f;

    float h[8];
#pragma unroll
    for (int k = 0; k < 8; k++)
        h[k] = fmaxf(fmaf(g_acc1[i * 8 + k], inv, __ldg(&b1[k])), 0.f);

    float o0 = 0.f, o1 = 0.f;
#pragma unroll
    for (int k = 0; k < 8; k++) {
        o0 = fmaf(h[k], __ldg(&W2[k * 2 + 0]), o0);
        o1 = fmaf(h[k], __ldg(&W2[k * 2 + 1]), o1);
    }
    g_h2[i] = make_float2(o0, o1);
    g_as2[i] = fmaf(o0, __ldg(&as2[0]), o1 * __ldg(&as2[1]));
    g_ad2[i] = fmaf(o0, __ldg(&ad2[0]), o1 * __ldg(&ad2[1]));
}

// ---- layer-2 edge kernel ----
__global__ __launch_bounds__(256) void k_edge2(const int* __restrict__ ei)
{
    const int e = blockIdx.x * 256 + threadIdx.x;
    if (e >= NE) return;
    const int s = ei[e];
    const int d = ei[NE + e];
    if ((unsigned)s >= NN || (unsigned)d >= NN) return;  // safety clamp

    float ev = g_as2[s] + g_ad2[d];
    ev = ev > 0.f ? ev : NEG * ev;
    const float w = __expf(ev);

    atomicAdd(&g_den2[d], w);
    const float2 h = g_h2[s];
    atomicAdd(&g_acc2[d * 2 + 0], w * h.x);
    atomicAdd(&g_acc2[d * 2 + 1], w * h.y);
}

// ---- final node kernel: normalize, +b2, log_softmax(2) ----
__global__ __launch_bounds__(256) void k_node3(
    const float* __restrict__ b2, float* __restrict__ out)
{
    const int i = blockIdx.x * 256 + threadIdx.x;
    if (i >= NN) return;

    const float den = g_den2[i];
    const float inv = den > 0.f ? 1.0f / den : 0.f;
    const float o0 = fmaf(g_acc2[i * 2 + 0], inv, __ldg(&b2[0]));
    const float o1 = fmaf(g_acc2[i * 2 + 1], inv, __ldg(&b2[1]));
    const float m = fmaxf(o0, o1);
    const float lse = m + logf(expf(o0 - m) + expf(o1 - m));
    ((float2*)out)[i] = make_float2(o0 - lse, o1 - lse);
}

extern "C" void kernel_launch(void* const* d_in, const int* in_sizes, int n_in,
                              void* d_out, int out_size)
{
    // ---- identify inputs by element count (robust to metadata ordering) ----
    int ix = -1, ie = -1, iw1 = -1, iw2 = -1;
    int i8[3] = {-1, -1, -1}, n8 = 0;
    int i2[3] = {-1, -1, -1}, n2 = 0;
    for (int i = 0; i < n_in; i++) {
        switch (in_sizes[i]) {
            case 3600000: ix = i; break;          // x [100000, 36] f32
            case 6400000: ie = i; break;          // edge_index [2, 3200000] i32
            case 288:     iw1 = i; break;         // W1 [36, 8]
            case 16:      iw2 = i; break;         // W2 [8, 2]
            case 8:  if (n8 < 3) i8[n8++] = i; break;  // a_src1/a_dst1/b1
            case 2:  if (n2 < 3) i2[n2++] = i; break;  // a_src2/a_dst2/b2
            default: break;
        }
    }
    // Tie-break within equal-size triples:
    //  dict/signature order (x first): a_src, a_dst, b
    //  alphabetical order (x last):    a_dst, a_src, b
    int ias1, iad1, ib1, ias2, iad2, ib2;
    if (ix == 0) { ias1 = i8[0]; iad1 = i8[1]; ib1 = i8[2];
                   ias2 = i2[0]; iad2 = i2[1]; ib2 = i2[2]; }
    else         { iad1 = i8[0]; ias1 = i8[1]; ib1 = i8[2];
                   iad2 = i2[0]; ias2 = i2[1]; ib2 = i2[2]; }

    const float* x   = (const float*)d_in[ix];
    const int*   ei  = (const int*)d_in[ie];     // int32 (JAX x64 disabled)
    const float* W1  = (const float*)d_in[iw1];
    const float* as1 = (const float*)d_in[ias1];
    const float* ad1 = (const float*)d_in[iad1];
    const float* b1  = (const float*)d_in[ib1];
    const float* W2  = (const float*)d_in[iw2];
    const float* as2 = (const float*)d_in[ias2];
    const float* ad2 = (const float*)d_in[iad2];
    const float* b2  = (const float*)d_in[ib2];
    float* out = (float*)d_out;

    const int nb_node1 = (NN + 127) / 128;
    const int nb_node  = (NN + 255) / 256;
    const int nb_edge  = (NE + 255) / 256;

    k_node1<<<nb_node1, 128>>>(x, W1, as1, ad1);
    k_edge1<<<nb_edge, 256>>>(ei);
    k_node2<<<nb_node, 256>>>(b1, W2, as2, ad2);
    k_edge2<<<nb_edge, 256>>>(ei);
    k_node3<<<nb_node, 256>>>(b2, out);
}

// round 6
// speedup vs baseline: 1.9757x; 1.9757x over previous
#include <cuda_runtime.h>

#define NN 100000
#define NE 3200000
#define NEG 0.2f

// ---- scratch (device globals; no allocations allowed) ----
__device__ __align__(16) float4 g_h1[NN * 2];     // h1 [NN,8]
__device__ float  g_as1[NN];
__device__ float  g_ad1[NN];
__device__ __align__(16) float4 g_acc1v[NN * 3];  // [0],[1]=vec acc, [2].x=den
__device__ __align__(16) float4 g_n2[NN];         // (h2x, h2y, as2, ad2)
__device__ __align__(16) float4 g_acc2v[NN];      // (accx, accy, den, pad)

// ---- layer-1 node kernel: h1 = x@W1, attention logits, zero accumulators ----
__global__ __launch_bounds__(128) void k_node1(
    const float* __restrict__ x, const float* __restrict__ W1,
    const float* __restrict__ as1, const float* __restrict__ ad1)
{
    __shared__ float xs[128 * 37];   // pad 36->37: conflict-free
    __shared__ float Ws[36 * 8];
    __shared__ float av[8], dv[8];
    const int t = threadIdx.x;
    const int base = blockIdx.x * 128;

    for (int i = t; i < 36 * 8; i += 128) Ws[i] = W1[i];
    if (t < 8) { av[t] = as1[t]; dv[t] = ad1[t]; }

    int nrows = NN - base; if (nrows > 128) nrows = 128;
    for (int i = t; i < nrows * 36; i += 128)
        xs[(i / 36) * 37 + (i % 36)] = x[base * 36 + i];
    __syncthreads();

    const int node = base + t;
    if (node >= NN) return;

    float h[8];
#pragma unroll
    for (int k = 0; k < 8; k++) h[k] = 0.f;
#pragma unroll
    for (int j = 0; j < 36; j++) {
        const float xv = xs[t * 37 + j];
#pragma unroll
        for (int k = 0; k < 8; k++) h[k] = fmaf(xv, Ws[j * 8 + k], h[k]);
    }
    g_h1[node * 2]     = make_float4(h[0], h[1], h[2], h[3]);
    g_h1[node * 2 + 1] = make_float4(h[4], h[5], h[6], h[7]);

    float s = 0.f, d = 0.f;
#pragma unroll
    for (int k = 0; k < 8; k++) { s = fmaf(h[k], av[k], s); d = fmaf(h[k], dv[k], d); }
    g_as1[node] = s;
    g_ad1[node] = d;

    const float4 z4 = make_float4(0.f, 0.f, 0.f, 0.f);
    g_acc1v[node * 3]     = z4;
    g_acc1v[node * 3 + 1] = z4;
    g_acc1v[node * 3 + 2] = z4;
    g_acc2v[node]         = z4;
}

// ---- layer-1 edge kernel: 2 x float4 RED + 1 scalar RED per edge ----
__global__ __launch_bounds__(256) void k_edge1(const int* __restrict__ ei)
{
    const int e = blockIdx.x * 256 + threadIdx.x;
    if (e >= NE) return;
    const int s = ei[e];
    const int d = ei[NE + e];
    if ((unsigned)s >= NN || (unsigned)d >= NN) return;  // safety clamp

    float ev = g_as1[s] + g_ad1[d];
    ev = ev > 0.f ? ev : NEG * ev;
    const float w = __expf(ev);

    const float4 h0 = g_h1[s * 2];
    const float4 h1 = g_h1[s * 2 + 1];
    atomicAdd(&g_acc1v[d * 3],
              make_float4(w * h0.x, w * h0.y, w * h0.z, w * h0.w));
    atomicAdd(&g_acc1v[d * 3 + 1],
              make_float4(w * h1.x, w * h1.y, w * h1.z, w * h1.w));
    atomicAdd((float*)&g_acc1v[d * 3 + 2], w);   // denom in .x
}

// ---- layer-2 node kernel: relu(agg1+b1) @ W2; pack (h2, as2, ad2) ----
__global__ __launch_bounds__(256) void k_node2(
    const float* __restrict__ b1, const float* __restrict__ W2,
    const float* __restrict__ as2, const float* __restrict__ ad2)
{
    const int i = blockIdx.x * 256 + threadIdx.x;
    if (i >= NN) return;

    const float4 a0 = g_acc1v[i * 3];
    const float4 a1 = g_acc1v[i * 3 + 1];
    const float den = g_acc1v[i * 3 + 2].x;
    const float inv = den > 0.f ? 1.0f / den : 0.f;

    float h[8];
    h[0] = fmaxf(fmaf(a0.x, inv, __ldg(&b1[0])), 0.f);
    h[1] = fmaxf(fmaf(a0.y, inv, __ldg(&b1[1])), 0.f);
    h[2] = fmaxf(fmaf(a0.z, inv, __ldg(&b1[2])), 0.f);
    h[3] = fmaxf(fmaf(a0.w, inv, __ldg(&b1[3])), 0.f);
    h[4] = fmaxf(fmaf(a1.x, inv, __ldg(&b1[4])), 0.f);
    h[5] = fmaxf(fmaf(a1.y, inv, __ldg(&b1[5])), 0.f);
    h[6] = fmaxf(fmaf(a1.z, inv, __ldg(&b1[6])), 0.f);
    h[7] = fmaxf(fmaf(a1.w, inv, __ldg(&b1[7])), 0.f);

    float o0 = 0.f, o1 = 0.f;
#pragma unroll
    for (int k = 0; k < 8; k++) {
        o0 = fmaf(h[k], __ldg(&W2[k * 2 + 0]), o0);
        o1 = fmaf(h[k], __ldg(&W2[k * 2 + 1]), o1);
    }
    const float s2 = fmaf(o0, __ldg(&as2[0]), o1 * __ldg(&as2[1]));
    const float d2 = fmaf(o0, __ldg(&ad2[0]), o1 * __ldg(&ad2[1]));
    g_n2[i] = make_float4(o0, o1, s2, d2);
}

// ---- layer-2 edge kernel: single float4 RED per edge ----
__global__ __launch_bounds__(256) void k_edge2(const int* __restrict__ ei)
{
    const int e = blockIdx.x * 256 + threadIdx.x;
    if (e >= NE) return;
    const int s = ei[e];
    const int d = ei[NE + e];
    if ((unsigned)s >= NN || (unsigned)d >= NN) return;  // safety clamp

    const float4 ns = g_n2[s];                 // h2x, h2y, as2, -
    const float  ad = g_n2[d].w;               // ad2
    float ev = ns.z + ad;
    ev = ev > 0.f ? ev : NEG * ev;
    const float w = __expf(ev);

    atomicAdd(&g_acc2v[d], make_float4(w * ns.x, w * ns.y, w, 0.f));
}

// ---- final node kernel: normalize, +b2, log_softmax(2) ----
__global__ __launch_bounds__(256) void k_node3(
    const float* __restrict__ b2, float* __restrict__ out)
{
    const int i = blockIdx.x * 256 + threadIdx.x;
    if (i >= NN) return;

    const float4 a = g_acc2v[i];
    const float inv = a.z > 0.f ? 1.0f / a.z : 0.f;
    const float o0 = fmaf(a.x, inv, __ldg(&b2[0]));
    const float o1 = fmaf(a.y, inv, __ldg(&b2[1]));
    const float m = fmaxf(o0, o1);
    const float lse = m + logf(expf(o0 - m) + expf(o1 - m));
    ((float2*)out)[i] = make_float2(o0 - lse, o1 - lse);
}

extern "C" void kernel_launch(void* const* d_in, const int* in_sizes, int n_in,
                              void* d_out, int out_size)
{
    // ---- identify inputs by element count (robust to metadata ordering) ----
    int ix = -1, ie = -1, iw1 = -1, iw2 = -1;
    int i8[3] = {-1, -1, -1}, n8 = 0;
    int i2[3] = {-1, -1, -1}, n2 = 0;
    for (int i = 0; i < n_in; i++) {
        switch (in_sizes[i]) {
            case 3600000: ix = i; break;          // x [100000, 36] f32
            case 6400000: ie = i; break;          // edge_index [2, 3200000] i32
            case 288:     iw1 = i; break;         // W1 [36, 8]
            case 16:      iw2 = i; break;         // W2 [8, 2]
            case 8:  if (n8 < 3) i8[n8++] = i; break;  // a_src1/a_dst1/b1
            case 2:  if (n2 < 3) i2[n2++] = i; break;  // a_src2/a_dst2/b2
            default: break;
        }
    }
    int ias1, iad1, ib1, ias2, iad2, ib2;
    if (ix == 0) { ias1 = i8[0]; iad1 = i8[1]; ib1 = i8[2];
                   ias2 = i2[0]; iad2 = i2[1]; ib2 = i2[2]; }
    else         { iad1 = i8[0]; ias1 = i8[1]; ib1 = i8[2];
                   iad2 = i2[0]; ias2 = i2[1]; ib2 = i2[2]; }

    const float* x   = (const float*)d_in[ix];
    const int*   ei  = (const int*)d_in[ie];     // int32 (JAX x64 disabled)
    const float* W1  = (const float*)d_in[iw1];
    const float* as1 = (const float*)d_in[ias1];
    const float* ad1 = (const float*)d_in[iad1];
    const float* b1  = (const float*)d_in[ib1];
    const float* W2  = (const float*)d_in[iw2];
    const float* as2 = (const float*)d_in[ias2];
    const float* ad2 = (const float*)d_in[iad2];
    const float* b2  = (const float*)d_in[ib2];
    float* out = (float*)d_out;

    const int nb_node1 = (NN + 127) / 128;
    const int nb_node  = (NN + 255) / 256;
    const int nb_edge  = (NE + 255) / 256;

    k_node1<<<nb_node1, 128>>>(x, W1, as1, ad1);
    k_edge1<<<nb_edge, 256>>>(ei);
    k_node2<<<nb_node, 256>>>(b1, W2, as2, ad2);
    k_edge2<<<nb_edge, 256>>>(ei);
    k_node3<<<nb_node, 256>>>(b2, out);
}